// round 10
// baseline (speedup 1.0000x reference)
#include <cuda_runtime.h>
#include <cuda_bf16.h>

// FastSpeech2 hard duration-based frame->token scalar averaging.
//   d_in[0] frame_scalar      float32 [B, 8192]
//   d_in[1] duration          float32 [B, 1024]
//   d_in[2] frame_scalar_len  int32   [B]
//   d_in[3] duration_len      int32   [B]
// Output: token_scalar float32 [B, 1024] (+ optional duration_len as f32 [B]).
//
// R10: champion R5 design (non-persistent, one CTA per row, deferred-offset
// scan, 6 CTAs/SM) with vectorized smem traffic and one barrier removed.
//  - pad +4 floats per 64 keeps 16B alignment -> STS.128/LDS.128 staging and
//    in-place chunk scan (4x fewer L1 wavefronts than scalar PAD layout)
//  - cross-warp offsets computed per-thread branch-free from s_wsum /
//    s_dwsum broadcast reads (no tid0 serial pass, 3 barriers total)

#define TFR 8192
#define TTK 1024
#define NTHREADS 256
#define CHF 32                  // frame elements per thread
#define CHF4 (CHF / 4)          // 8 float4 per thread
#define CHT 4                   // tokens per thread
#define NWARPS (NTHREADS / 32)

// +4 floats of padding per 64: PAD(i) = i + ((i>>6)<<2).
// A thread's 32-float chunk lies in one 64-block -> stays contiguous and
// 16B-aligned; staging/scan vector ops are (at worst 2-way) conflict-light.
__device__ __forceinline__ int PAD(int i) { return i + ((i >> 6) << 2); }
#define CFS_SLOTS (8191 + ((8191 >> 6) << 2) + 1)   // 8700 floats = 34.8 KB

__global__ __launch_bounds__(NTHREADS, 6)
void fs2_dur_avg_kernel(const float* __restrict__ frame_scalar,
                        const float* __restrict__ duration,
                        const int*   __restrict__ frame_scalar_len,
                        const int*   __restrict__ duration_len,
                        float*       __restrict__ out,
                        int B, int write_extra)
{
    __shared__ __align__(16) float s_cfs[CFS_SLOTS]; // local chunk prefixes
    __shared__ float s_toff[NTHREADS];   // exclusive offset of each 32-chunk
    __shared__ float s_wsum[NWARPS];     // frame warp totals
    __shared__ float s_dwsum[NWARPS];    // duration warp totals

    const int row  = blockIdx.x;
    const int tid  = threadIdx.x;
    const int lane = tid & 31;
    const int wid  = tid >> 5;

    // ---------- Phase 1: stage frame row (LDG.128 -> STS.128, padded) ------
    {
        const float4* fs4 = reinterpret_cast<const float4*>(
            frame_scalar + (size_t)row * TFR);
        #pragma unroll
        for (int k = 0; k < CHF4; k++) {
            const int v4idx = tid + k * NTHREADS;       // coalesced 512B/warp
            const float4 v = fs4[v4idx];
            const int fidx = v4idx * 4;
            *reinterpret_cast<float4*>(&s_cfs[PAD(fidx)]) = v;
        }
    }

    // ---------- duration load + per-thread/warp cumsum (pre-barrier) -------
    const float4 d4 = reinterpret_cast<const float4*>(
                          duration + (size_t)row * TTK)[tid];
    const int   dl = duration_len[row];
    const float fl = (float)frame_scalar_len[row];

    float dv[CHT], p[CHT], d_excl;
    {
        const float din[CHT] = {d4.x, d4.y, d4.z, d4.w};
        const int jbase = tid * CHT;
        #pragma unroll
        for (int k = 0; k < CHT; k++) {
            // round half-to-even (jnp.round), clamp >=0, zero past dlen
            const float r = fmaxf(rintf(din[k]), 0.0f);
            dv[k] = (jbase + k < dl) ? r : 0.0f;
        }
        float run = 0.0f;
        #pragma unroll
        for (int k = 0; k < CHT; k++) { run += dv[k]; p[k] = run; }
        float incl = run;
        #pragma unroll
        for (int d = 1; d < 32; d <<= 1) {
            const float t = __shfl_up_sync(0xffffffffu, incl, d);
            if (lane >= d) incl += t;
        }
        if (lane == 31) s_dwsum[wid] = incl;
        d_excl = incl - run;                 // exclusive offset within warp
    }
    __syncthreads();                         // staging + s_dwsum visible

    // ---------- Phase 2: in-place vector chunk scan + warp totals ----------
    {
        float4* cp = reinterpret_cast<float4*>(&s_cfs[PAD(tid * CHF)]);
        float run = 0.0f;
        #pragma unroll
        for (int k = 0; k < CHF4; k++) {
            float4 v = cp[k];                // LDS.128
            const float s1 = run + v.x;
            const float s2 = s1 + v.y;
            const float s3 = s2 + v.z;
            const float s4 = s3 + v.w;
            v.x = s1; v.y = s2; v.z = s3; v.w = s4;
            cp[k] = v;                       // STS.128 (local inclusive prefix)
            run = s4;
        }
        const float tot = run;
        float incl = tot;
        #pragma unroll
        for (int d = 1; d < 32; d <<= 1) {
            const float t = __shfl_up_sync(0xffffffffu, incl, d);
            if (lane >= d) incl += t;
        }
        if (lane == 31) s_wsum[wid] = incl;
        __syncthreads();                     // s_wsum visible

        // Cross-warp frame offset: branch-free ascending sum (same FP order
        // as the old serial tid0 pass -> bit-identical results).
        float woff = 0.0f;
        #pragma unroll
        for (int i = 0; i < NWARPS - 1; i++) {
            const float take = (i < wid) ? 1.0f : 0.0f;
            woff += take * s_wsum[i];
        }
        s_toff[tid] = woff + (incl - tot);   // exclusive offset of chunk tid
    }

    // Cross-warp duration offset (s_dwsum valid since barrier 1).
    float doff = d_excl;
    #pragma unroll
    for (int i = 0; i < NWARPS - 1; i++) {
        const float take = (i < wid) ? 1.0f : 0.0f;
        doff += take * s_dwsum[i];
    }
    __syncthreads();                         // s_toff visible
    // cfs(e) := sum frame[0..e) =
    //   (e==0) ? 0 : s_cfs[PAD(e-1)] + s_toff[(e-1) >> 5]

    // ---------- Phase 3: gather --------------------------------------------
    {
        float4 res;
        float* rp = reinterpret_cast<float*>(&res);
        #pragma unroll
        for (int k = 0; k < CHT; k++) {
            const float cend_raw   = doff + p[k];       // cumsum thru token j
            const float cstart_raw = cend_raw - dv[k];  // cumsum thru j-1
            const float endf   = fminf(cend_raw, fl);
            const float startf = fminf(cstart_raw, fl);
            const float dlen_f = endf - startf;         // exact int-valued
            const int e = (int)endf;
            const int s = (int)startf;
            const float cfs_e = (e == 0) ? 0.0f
                              : s_cfs[PAD(e - 1)] + s_toff[(e - 1) >> 5];
            const float cfs_s = (s == 0) ? 0.0f
                              : s_cfs[PAD(s - 1)] + s_toff[(s - 1) >> 5];
            const float seg = cfs_e - cfs_s;
            rp[k] = (dlen_f > 0.0f) ? seg / fmaxf(dlen_f, 1.0f) : 0.0f;
        }
        reinterpret_cast<float4*>(out + (size_t)row * TTK)[tid] = res;
    }

    // Optional second tuple output: duration_len (numeric cast to f32).
    if (write_extra && tid == 0)
        out[(size_t)B * TTK + row] = (float)dl;
}

extern "C" void kernel_launch(void* const* d_in, const int* in_sizes, int n_in,
                              void* d_out, int out_size) {
    const float* frame_scalar     = (const float*)d_in[0];
    const float* duration         = (const float*)d_in[1];
    const int*   frame_scalar_len = (const int*)d_in[2];
    const int*   duration_len     = (const int*)d_in[3];
    float* out = (float*)d_out;

    const int B = in_sizes[2];                       // [B] int32
    const int write_extra = (out_size > B * TTK) ? 1 : 0;

    fs2_dur_avg_kernel<<<B, NTHREADS>>>(frame_scalar, duration,
                                        frame_scalar_len, duration_len,
                                        out, B, write_extra);
}

// round 11
// speedup vs baseline: 1.3643x; 1.3643x over previous
#include <cuda_runtime.h>
#include <cuda_bf16.h>

// FastSpeech2 hard duration-based frame->token scalar averaging.
//   d_in[0] frame_scalar      float32 [B, 8192]
//   d_in[1] duration          float32 [B, 1024]
//   d_in[2] frame_scalar_len  int32   [B]
//   d_in[3] duration_len      int32   [B]
// Output: token_scalar float32 [B, 1024] (+ optional duration_len as f32 [B]).
//
// R11: back to the measured-best R4 layout (scalar +1/32 PAD, deferred chunk
// offsets, 6 CTAs/SM, one CTA per row, non-persistent) PLUS dead-read
// elimination: the gather only touches frame indices < needed =
// min(total_duration, frame_scalar_len)  (E[needed] ~ 8192/3). Duration
// cumsum runs FIRST; frame loads and the scan cover only
// ceil(needed/1024)*1024 elements -> ~3x less frame DRAM traffic on average.

#define TFR 8192
#define TTK 1024
#define NTHREADS 256
#define CHF (TFR / NTHREADS)   // 32 frame elements per thread-chunk
#define CHT (TTK / NTHREADS)   // 4 tokens per thread
#define NWARPS (NTHREADS / 32)

// Padded smem addressing (+1 float per 32): conflict-free striped writes,
// contiguous-chunk scan, and low-conflict random gather. (Measured best.)
__device__ __forceinline__ int PAD(int i) { return i + (i >> 5); }
#define CFS_SLOTS (TFR - 1 + ((TFR - 1) >> 5) + 1)   // PAD(8191)+1 = 8447

__global__ __launch_bounds__(NTHREADS, 6)
void fs2_dur_avg_kernel(const float* __restrict__ frame_scalar,
                        const float* __restrict__ duration,
                        const int*   __restrict__ frame_scalar_len,
                        const int*   __restrict__ duration_len,
                        float*       __restrict__ out,
                        int B, int write_extra)
{
    __shared__ float s_cfs[CFS_SLOTS];   // local (per-chunk) inclusive prefixes
    __shared__ float s_toff[NTHREADS];   // exclusive offset of each 32-chunk
    __shared__ float s_wsum[NWARPS];     // frame warp totals
    __shared__ float s_dwsum[NWARPS];    // duration warp totals

    const int row  = blockIdx.x;
    const int tid  = threadIdx.x;
    const int lane = tid & 31;
    const int wid  = tid >> 5;

    // ---------- Phase 0: duration cumsum FIRST (bounds the frame read) -----
    const float4 d4 = reinterpret_cast<const float4*>(
                          duration + (size_t)row * TTK)[tid];
    const int   dl = duration_len[row];
    const float fl = (float)frame_scalar_len[row];

    float dv[CHT], p[CHT], d_excl;
    {
        const float din[CHT] = {d4.x, d4.y, d4.z, d4.w};
        const int jbase = tid * CHT;
        #pragma unroll
        for (int k = 0; k < CHT; k++) {
            // round half-to-even (jnp.round), clamp >=0, zero past dlen
            const float r = fmaxf(rintf(din[k]), 0.0f);
            dv[k] = (jbase + k < dl) ? r : 0.0f;
        }
        float run = 0.0f;
        #pragma unroll
        for (int k = 0; k < CHT; k++) { run += dv[k]; p[k] = run; }
        float incl = run;
        #pragma unroll
        for (int d = 1; d < 32; d <<= 1) {
            const float t = __shfl_up_sync(0xffffffffu, incl, d);
            if (lane >= d) incl += t;
        }
        if (lane == 31) s_dwsum[wid] = incl;
        d_excl = incl - run;                 // exclusive offset within warp
    }
    __syncthreads();                         // s_dwsum visible

    // Every thread: total duration + its cross-warp offset (ascending order,
    // exact integer-valued sums -> deterministic and bit-stable).
    float dur_total = 0.0f;
    float doff = d_excl;
    #pragma unroll
    for (int i = 0; i < NWARPS; i++) {
        const float v = s_dwsum[i];
        dur_total += v;
        if (i < wid) doff += v;
    }

    // Frames actually referenced: indices < needed.
    const int needed = (int)fminf(dur_total, fl);
    const int kmax   = (needed + 1023) >> 10;        // 1024-float load blocks

    // ---------- Phase 1: stage ONLY the needed frame blocks ---------------
    {
        const float4* fs4 = reinterpret_cast<const float4*>(
            frame_scalar + (size_t)row * TFR);
        for (int k = 0; k < kmax; k++) {             // <= 8 iterations
            const int v4idx = tid + (k << 8);        // coalesced 512B/warp
            const float4 w = fs4[v4idx];
            const int fidx = v4idx * 4;
            s_cfs[PAD(fidx + 0)] = w.x;
            s_cfs[PAD(fidx + 1)] = w.y;
            s_cfs[PAD(fidx + 2)] = w.z;
            s_cfs[PAD(fidx + 3)] = w.w;
        }
    }
    __syncthreads();                         // staging visible

    // ---------- Phase 2: local chunk scan over needed region ---------------
    {
        const int base = tid * CHF;
        float tot = 0.0f;
        if (base < needed) {                 // whole-warp-uniform at 1024 gran,
            float run = 0.0f;                // straddle warps diverge harmlessly
            #pragma unroll
            for (int k = 0; k < CHF; k++) {
                const int i = PAD(base + k);          // conflict-free
                run += s_cfs[i];
                s_cfs[i] = run;                       // local inclusive prefix
            }
            tot = run;
        }
        float incl = tot;
        #pragma unroll
        for (int d = 1; d < 32; d <<= 1) {
            const float t = __shfl_up_sync(0xffffffffu, incl, d);
            if (lane >= d) incl += t;
        }
        if (lane == 31) s_wsum[wid] = incl;
        __syncthreads();                     // s_wsum visible

        // Cross-warp frame offset, branch-free ascending sum.
        float woff = 0.0f;
        #pragma unroll
        for (int i = 0; i < NWARPS - 1; i++) {
            const float take = (i < wid) ? 1.0f : 0.0f;
            woff += take * s_wsum[i];
        }
        s_toff[tid] = woff + (incl - tot);   // exclusive offset of chunk tid
    }
    __syncthreads();                         // s_toff visible
    // cfs(e) := sum frame[0..e) = (e==0) ? 0
    //         : s_cfs[PAD(e-1)] + s_toff[(e-1) >> 5]   (valid for e <= needed)

    // ---------- Phase 3: gather --------------------------------------------
    {
        float4 res;
        float* rp = reinterpret_cast<float*>(&res);
        #pragma unroll
        for (int k = 0; k < CHT; k++) {
            const float cend_raw   = doff + p[k];       // cumsum thru token j
            const float cstart_raw = cend_raw - dv[k];  // cumsum thru j-1
            const float endf   = fminf(cend_raw, fl);
            const float startf = fminf(cstart_raw, fl);
            const float dlen_f = endf - startf;         // exact int-valued
            const int e = (int)endf;                    // e <= needed
            const int s = (int)startf;
            const float cfs_e = (e == 0) ? 0.0f
                              : s_cfs[PAD(e - 1)] + s_toff[(e - 1) >> 5];
            const float cfs_s = (s == 0) ? 0.0f
                              : s_cfs[PAD(s - 1)] + s_toff[(s - 1) >> 5];
            const float seg = cfs_e - cfs_s;
            rp[k] = (dlen_f > 0.0f) ? seg / fmaxf(dlen_f, 1.0f) : 0.0f;
        }
        reinterpret_cast<float4*>(out + (size_t)row * TTK)[tid] = res;
    }

    // Optional second tuple output: duration_len (numeric cast to f32).
    if (write_extra && tid == 0)
        out[(size_t)B * TTK + row] = (float)dl;
}

extern "C" void kernel_launch(void* const* d_in, const int* in_sizes, int n_in,
                              void* d_out, int out_size) {
    const float* frame_scalar     = (const float*)d_in[0];
    const float* duration         = (const float*)d_in[1];
    const int*   frame_scalar_len = (const int*)d_in[2];
    const int*   duration_len     = (const int*)d_in[3];
    float* out = (float*)d_out;

    const int B = in_sizes[2];                       // [B] int32
    const int write_extra = (out_size > B * TTK) ? 1 : 0;

    fs2_dur_avg_kernel<<<B, NTHREADS>>>(frame_scalar, duration,
                                        frame_scalar_len, duration_len,
                                        out, B, write_extra);
}

// round 12
// speedup vs baseline: 1.5338x; 1.1242x over previous
#include <cuda_runtime.h>
#include <cuda_bf16.h>

// FastSpeech2 hard duration-based frame->token scalar averaging.
//   d_in[0] frame_scalar      float32 [B, 8192]
//   d_in[1] duration          float32 [B, 1024]
//   d_in[2] frame_scalar_len  int32   [B]
//   d_in[3] duration_len      int32   [B]
// Output: token_scalar float32 [B, 1024] (+ optional duration_len as f32 [B]).
//
// R12: bounded-read (R11) + scan-free direct segment-sum gather (R8 compute)
// + cp.async staging with 2-block speculation to overlap the duration
// dependency. One CTA per row, non-persistent, 32KB smem, 2 barriers.

#define TFR 8192
#define TTK 1024
#define NTHREADS 256
#define CHT 4                    // tokens per thread
#define NWARPS (NTHREADS / 32)
#define SPEC_BLOCKS 2            // speculative 1024-float blocks (E[kmax]=2.7)

__global__ __launch_bounds__(NTHREADS)
void fs2_dur_avg_kernel(const float* __restrict__ frame_scalar,
                        const float* __restrict__ duration,
                        const int*   __restrict__ frame_scalar_len,
                        const int*   __restrict__ duration_len,
                        float*       __restrict__ out,
                        int B, int write_extra)
{
    __shared__ __align__(16) float s_buf[TFR];   // staged frame row (plain)
    __shared__ float s_dwsum[NWARPS];            // duration warp totals

    const int row  = blockIdx.x;
    const int tid  = threadIdx.x;
    const int lane = tid & 31;
    const int wid  = tid >> 5;

    const float* fsrow = frame_scalar + (size_t)row * TFR;
    const unsigned smb = (unsigned)__cvta_generic_to_shared(s_buf);

    // ---- speculative cp.async of first SPEC_BLOCKS frame blocks ----------
    // (fire-and-forget; overlaps the duration load + cumsum below)
    #pragma unroll
    for (int k = 0; k < SPEC_BLOCKS; k++) {
        const int idx = (k << 10) + (tid << 2);          // k*1024 + tid*4
        asm volatile("cp.async.cg.shared.global [%0], [%1], 16;\n"
                     :: "r"(smb + idx * 4), "l"(fsrow + idx));
    }
    asm volatile("cp.async.commit_group;\n");

    // ---- duration load + per-thread/warp cumsum ---------------------------
    const float4 d4 = reinterpret_cast<const float4*>(
                          duration + (size_t)row * TTK)[tid];
    const int   dl = duration_len[row];
    const float fl = (float)frame_scalar_len[row];

    float dv[CHT], p[CHT], d_excl;
    {
        const float din[CHT] = {d4.x, d4.y, d4.z, d4.w};
        const int jbase = tid * CHT;
        #pragma unroll
        for (int k = 0; k < CHT; k++) {
            // round half-to-even (jnp.round), clamp >=0, zero past dlen
            const float r = fmaxf(rintf(din[k]), 0.0f);
            dv[k] = (jbase + k < dl) ? r : 0.0f;
        }
        float run = 0.0f;
        #pragma unroll
        for (int k = 0; k < CHT; k++) { run += dv[k]; p[k] = run; }
        float incl = run;
        #pragma unroll
        for (int d = 1; d < 32; d <<= 1) {
            const float t = __shfl_up_sync(0xffffffffu, incl, d);
            if (lane >= d) incl += t;
        }
        if (lane == 31) s_dwsum[wid] = incl;
        d_excl = incl - run;                 // exclusive offset within warp
    }
    __syncthreads();                         // s_dwsum visible

    // Total duration + this thread's cross-warp offset (ascending order,
    // exact integer-valued sums -> deterministic).
    float dur_total = 0.0f;
    float doff = d_excl;
    #pragma unroll
    for (int i = 0; i < NWARPS; i++) {
        const float v = s_dwsum[i];
        dur_total += v;
        if (i < wid) doff += v;
    }

    // Frames actually referenced: indices < needed.
    const int needed = (int)fminf(dur_total, fl);
    const int kmax   = (needed + 1023) >> 10;        // 1024-float blocks

    // ---- stage remaining needed blocks (cp.async, all in flight) ----------
    for (int k = SPEC_BLOCKS; k < kmax; k++) {
        const int idx = (k << 10) + (tid << 2);
        asm volatile("cp.async.cg.shared.global [%0], [%1], 16;\n"
                     :: "r"(smb + idx * 4), "l"(fsrow + idx));
    }
    asm volatile("cp.async.commit_group;\n");
    asm volatile("cp.async.wait_group 0;\n");        // all staging complete
    __syncthreads();

    // ---- gather: direct segment sums from smem ----------------------------
    {
        float4 res;
        float* rp = reinterpret_cast<float*>(&res);
        #pragma unroll
        for (int k = 0; k < CHT; k++) {
            const float cend_raw   = doff + p[k];       // cumsum thru token j
            const float cstart_raw = cend_raw - dv[k];  // cumsum thru j-1
            const float endf   = fminf(cend_raw, fl);
            const float startf = fminf(cstart_raw, fl);
            const float dlen_f = endf - startf;         // exact int-valued
            const int e = (int)endf;                    // e <= needed
            const int s = (int)startf;
            float sum = 0.0f;
            for (int i = s; i < e; i++) sum += s_buf[i];
            rp[k] = (dlen_f > 0.0f) ? sum / fmaxf(dlen_f, 1.0f) : 0.0f;
        }
        reinterpret_cast<float4*>(out + (size_t)row * TTK)[tid] = res;
    }

    // Optional second tuple output: duration_len (numeric cast to f32).
    if (write_extra && tid == 0)
        out[(size_t)B * TTK + row] = (float)dl;
}

extern "C" void kernel_launch(void* const* d_in, const int* in_sizes, int n_in,
                              void* d_out, int out_size) {
    const float* frame_scalar     = (const float*)d_in[0];
    const float* duration         = (const float*)d_in[1];
    const int*   frame_scalar_len = (const int*)d_in[2];
    const int*   duration_len     = (const int*)d_in[3];
    float* out = (float*)d_out;

    const int B = in_sizes[2];                       // [B] int32
    const int write_extra = (out_size > B * TTK) ? 1 : 0;

    fs2_dur_avg_kernel<<<B, NTHREADS>>>(frame_scalar, duration,
                                        frame_scalar_len, duration_len,
                                        out, B, write_extra);
}